// round 5
// baseline (speedup 1.0000x reference)
#include <cuda_runtime.h>
#include <cuda_bf16.h>
#include <cstdint>

#define MAX_NODES 100000

__device__ float g_agg[MAX_NODES * 64];
__device__ __nv_bfloat16 g_wh[90112];
__device__ __nv_bfloat16 g_wl[90112];

#define OFF_EW1 0
#define OFF_EW2 24576
#define OFF_EW3 40960
#define OFF_NW1 49152
#define OFF_NW2 65536
#define OFF_NW3 81920

// ---------------------------------------------------------------------------
__global__ void __launch_bounds__(256) zero_agg_kernel(int n4) {
    int i = blockIdx.x * 256 + threadIdx.x;
    if (i < n4) reinterpret_cast<float4*>(g_agg)[i] = make_float4(0.f, 0.f, 0.f, 0.f);
}
__global__ void pad_kernel() {}

// fused: transpose W[k][n] -> Wt[n][k], split fp32 = bf16_hi + bf16_lo
__global__ void __launch_bounds__(256) prep_kernel(
    const float* __restrict__ ew1, const float* __restrict__ ew2,
    const float* __restrict__ ew3, const float* __restrict__ nw1,
    const float* __restrict__ nw2, const float* __restrict__ nw3)
{
    int i = blockIdx.x * 256 + threadIdx.x;
    if (i >= 90112) return;
    const float* W; int K, N, li;
    if      (i < 24576) { W = ew1; K = 192; N = 128; li = i; }
    else if (i < 40960) { W = ew2; K = 128; N = 128; li = i - 24576; }
    else if (i < 49152) { W = ew3; K = 128; N = 64;  li = i - 40960; }
    else if (i < 65536) { W = nw1; K = 128; N = 128; li = i - 49152; }
    else if (i < 81920) { W = nw2; K = 128; N = 128; li = i - 65536; }
    else                { W = nw3; K = 128; N = 64;  li = i - 81920; }
    int n = li / K, k = li - n * K;
    float v = W[(size_t)k * N + n];
    __nv_bfloat16 h = __float2bfloat16_rn(v);
    g_wh[i] = h;
    g_wl[i] = __float2bfloat16_rn(v - __bfloat162float(h));
}

// ---------------------------------------------------------------------------
__device__ __forceinline__ uint32_t smem_u32(const void* p) {
    uint32_t a;
    asm("{ .reg .u64 t; cvta.to.shared.u64 t, %1; cvt.u32.u64 %0, t; }"
        : "=r"(a) : "l"(p));
    return a;
}

__device__ __forceinline__ void split2(float x, float y, uint32_t& h, uint32_t& l) {
    __nv_bfloat162 hh = __floats2bfloat162_rn(x, y);
    float rx = x - __bfloat162float(hh.x);
    float ry = y - __bfloat162float(hh.y);
    __nv_bfloat162 ll = __floats2bfloat162_rn(rx, ry);
    h = reinterpret_cast<uint32_t&>(hh);
    l = reinterpret_cast<uint32_t&>(ll);
}

__device__ __forceinline__ float tanhf_fast(float x) {
    float e;
    asm("ex2.approx.f32 %0, %1;" : "=f"(e) : "f"(x * 2.885390082f)); // exp(2x)
    return 1.0f - __fdividef(2.0f, e + 1.0f);
}

__device__ __forceinline__ void mma16816(float* d, const uint32_t* a,
                                         uint32_t b0, uint32_t b1) {
    asm volatile(
        "mma.sync.aligned.m16n8k16.row.col.f32.bf16.bf16.f32 "
        "{%0,%1,%2,%3}, {%4,%5,%6,%7}, {%8,%9}, {%0,%1,%2,%3};\n"
        : "+f"(d[0]), "+f"(d[1]), "+f"(d[2]), "+f"(d[3])
        : "r"(a[0]), "r"(a[1]), "r"(a[2]), "r"(a[3]), "r"(b0), "r"(b1));
}

__device__ __forceinline__ void ldm4(uint32_t* r, uint32_t addr) {
    asm volatile("ldmatrix.sync.aligned.m8n8.x4.shared.b16 {%0,%1,%2,%3}, [%4];"
                 : "=r"(r[0]), "=r"(r[1]), "=r"(r[2]), "=r"(r[3]) : "r"(addr));
}

#define CP16(dst, src) \
    asm volatile("cp.async.cg.shared.global [%0], [%1], 16;" \
                 :: "r"(dst), "l"(src) : "memory")
#define CP_WAIT() \
    asm volatile("cp.async.commit_group;\n cp.async.wait_group 0;" ::: "memory")

// ---------------------------------------------------------------------------
// C=128 layer. 256 thr = 8 warps, M tile = 128.
// warp w: nhalf = w&1 (64 n-cols), m-strips {(w>>1)*16, +64}.
// Per k-step: prefetch ALL fragments, then issue MMAs grouped by split term
// (16 independent MMAs between accumulator reuse -> no RAW chains).
// ---------------------------------------------------------------------------
template <int K>
__device__ __forceinline__ void layer_c128(
    const __nv_bfloat16* __restrict__ Wh, const __nv_bfloat16* __restrict__ Wl,
    __nv_bfloat16* s_ah, __nv_bfloat16* s_al, int AS,
    __nv_bfloat16* s_wh, __nv_bfloat16* s_wl,
    const float* __restrict__ bias, int tid)
{
    const int lane = tid & 31, w = tid >> 5;
    const int g = lane >> 2, t = lane & 3;
    const int nhalf = w & 1, mb0 = (w >> 1) << 4;
    const int aro = (lane & 7) + (((lane >> 3) & 1) << 3);
    const int ako = (lane >> 4) << 3;
    const int bro = (lane & 7) + ((lane >> 4) << 3);
    const int bko = ((lane >> 3) & 1) << 3;
    const uint32_t u_ah = smem_u32(s_ah), u_al = smem_u32(s_al);
    const uint32_t u_wh = smem_u32(s_wh), u_wl = smem_u32(s_wl);

    float acc[2][8][4] = {};

    #pragma unroll
    for (int kc = 0; kc < (K >> 6); kc++) {
        __syncthreads();
        {
            const __nv_bfloat16* sh = Wh + (kc << 6);
            const __nv_bfloat16* sl = Wl + (kc << 6);
            #pragma unroll
            for (int i = 0; i < 4; i++) {
                int idx = tid + (i << 8);
                int n = idx >> 3, k8 = (idx & 7) << 3;
                CP16(u_wh + (uint32_t)(n * 72 + k8) * 2, sh + (size_t)n * K + k8);
                CP16(u_wl + (uint32_t)(n * 72 + k8) * 2, sl + (size_t)n * K + k8);
            }
            CP_WAIT();
        }
        __syncthreads();
        #pragma unroll
        for (int ks = 0; ks < 4; ks++) {
            const int ka = (kc << 6) + (ks << 4);
            const int kw = ks << 4;
            // prefetch all fragments for this k-step
            uint32_t ah[2][4], al[2][4];
            #pragma unroll
            for (int s = 0; s < 2; s++) {
                uint32_t aoff = (uint32_t)((mb0 + (s << 6) + aro) * AS + ka + ako) * 2;
                ldm4(ah[s], u_ah + aoff);
                ldm4(al[s], u_al + aoff);
            }
            uint32_t bh[4][4], bl[4][4];
            #pragma unroll
            for (int np = 0; np < 4; np++) {
                uint32_t boff = (uint32_t)((((nhalf << 6) + (np << 4)) + bro) * 72 + kw + bko) * 2;
                ldm4(bh[np], u_wh + boff);
                ldm4(bl[np], u_wl + boff);
            }
            // term 1: ah * bh  (16 independent MMAs)
            #pragma unroll
            for (int np = 0; np < 4; np++)
                #pragma unroll
                for (int s = 0; s < 2; s++) {
                    mma16816(acc[s][2 * np],     ah[s], bh[np][0], bh[np][1]);
                    mma16816(acc[s][2 * np + 1], ah[s], bh[np][2], bh[np][3]);
                }
            // term 2: ah * bl
            #pragma unroll
            for (int np = 0; np < 4; np++)
                #pragma unroll
                for (int s = 0; s < 2; s++) {
                    mma16816(acc[s][2 * np],     ah[s], bl[np][0], bl[np][1]);
                    mma16816(acc[s][2 * np + 1], ah[s], bl[np][2], bl[np][3]);
                }
            // term 3: al * bh
            #pragma unroll
            for (int np = 0; np < 4; np++)
                #pragma unroll
                for (int s = 0; s < 2; s++) {
                    mma16816(acc[s][2 * np],     al[s], bh[np][0], bh[np][1]);
                    mma16816(acc[s][2 * np + 1], al[s], bh[np][2], bh[np][3]);
                }
        }
    }
    // epilogue: bias + tanh, split-store back into s_ah/s_al
    __syncthreads();
    #pragma unroll
    for (int nt = 0; nt < 8; nt++) {
        int col = (nhalf << 6) + (nt << 3) + (t << 1);
        float2 bb = *reinterpret_cast<const float2*>(&bias[col]);
        #pragma unroll
        for (int s = 0; s < 2; s++) {
            int r = mb0 + (s << 6) + g;
            uint32_t h, l;
            split2(tanhf_fast(acc[s][nt][0] + bb.x), tanhf_fast(acc[s][nt][1] + bb.y), h, l);
            *reinterpret_cast<uint32_t*>(&s_ah[r * AS + col]) = h;
            *reinterpret_cast<uint32_t*>(&s_al[r * AS + col]) = l;
            split2(tanhf_fast(acc[s][nt][2] + bb.x), tanhf_fast(acc[s][nt][3] + bb.y), h, l);
            *reinterpret_cast<uint32_t*>(&s_ah[(r + 8) * AS + col]) = h;
            *reinterpret_cast<uint32_t*>(&s_al[(r + 8) * AS + col]) = l;
        }
    }
    __syncthreads();
}

// ---------------------------------------------------------------------------
// C=64 final layer, K=128. Weights [64n][136k-stride] fully staged.
// ---------------------------------------------------------------------------
__device__ __forceinline__ void layer_c64(
    const __nv_bfloat16* __restrict__ Wh, const __nv_bfloat16* __restrict__ Wl,
    const __nv_bfloat16* s_ah, const __nv_bfloat16* s_al, int AS,
    __nv_bfloat16* s_wh, __nv_bfloat16* s_wl,
    const float* __restrict__ bias, float* s_out, int tid)
{
    const int lane = tid & 31, w = tid >> 5;
    const int g = lane >> 2, t = lane & 3;
    const int nhalf = w & 1, mb0 = (w >> 1) << 4;
    const int aro = (lane & 7) + (((lane >> 3) & 1) << 3);
    const int ako = (lane >> 4) << 3;
    const int bro = (lane & 7) + ((lane >> 4) << 3);
    const int bko = ((lane >> 3) & 1) << 3;
    const uint32_t u_ah = smem_u32(s_ah), u_al = smem_u32(s_al);
    const uint32_t u_wh = smem_u32(s_wh), u_wl = smem_u32(s_wl);

    float acc[2][4][4] = {};

    __syncthreads();
    #pragma unroll
    for (int i = 0; i < 4; i++) {
        int idx = tid + (i << 8);
        int n = idx >> 4, k8 = (idx & 15) << 3;
        CP16(u_wh + (uint32_t)(n * 136 + k8) * 2, Wh + (size_t)n * 128 + k8);
        CP16(u_wl + (uint32_t)(n * 136 + k8) * 2, Wl + (size_t)n * 128 + k8);
    }
    CP_WAIT();
    __syncthreads();

    #pragma unroll
    for (int ks = 0; ks < 8; ks++) {
        const int ka = ks << 4;
        uint32_t ah[2][4], al[2][4];
        #pragma unroll
        for (int s = 0; s < 2; s++) {
            uint32_t aoff = (uint32_t)((mb0 + (s << 6) + aro) * AS + ka + ako) * 2;
            ldm4(ah[s], u_ah + aoff);
            ldm4(al[s], u_al + aoff);
        }
        uint32_t bh[2][4], bl[2][4];
        #pragma unroll
        for (int np = 0; np < 2; np++) {
            uint32_t boff = (uint32_t)((((nhalf << 5) + (np << 4)) + bro) * 136 + ka + bko) * 2;
            ldm4(bh[np], u_wh + boff);
            ldm4(bl[np], u_wl + boff);
        }
        #pragma unroll
        for (int np = 0; np < 2; np++)
            #pragma unroll
            for (int s = 0; s < 2; s++) {
                mma16816(acc[s][2 * np],     ah[s], bh[np][0], bh[np][1]);
                mma16816(acc[s][2 * np + 1], ah[s], bh[np][2], bh[np][3]);
            }
        #pragma unroll
        for (int np = 0; np < 2; np++)
            #pragma unroll
            for (int s = 0; s < 2; s++) {
                mma16816(acc[s][2 * np],     ah[s], bl[np][0], bl[np][1]);
                mma16816(acc[s][2 * np + 1], ah[s], bl[np][2], bl[np][3]);
            }
        #pragma unroll
        for (int np = 0; np < 2; np++)
            #pragma unroll
            for (int s = 0; s < 2; s++) {
                mma16816(acc[s][2 * np],     al[s], bh[np][0], bh[np][1]);
                mma16816(acc[s][2 * np + 1], al[s], bh[np][2], bh[np][3]);
            }
    }
    __syncthreads();  // done reading weights; s_out aliases the weight region
    #pragma unroll
    for (int nt = 0; nt < 4; nt++) {
        int col = (nhalf << 5) + (nt << 3) + (t << 1);
        float2 bb = *reinterpret_cast<const float2*>(&bias[col]);
        #pragma unroll
        for (int s = 0; s < 2; s++) {
            int r = mb0 + (s << 6) + g;
            *reinterpret_cast<float2*>(&s_out[r * 68 + col]) =
                make_float2(acc[s][nt][0] + bb.x, acc[s][nt][1] + bb.y);
            *reinterpret_cast<float2*>(&s_out[(r + 8) * 68 + col]) =
                make_float2(acc[s][nt][2] + bb.x, acc[s][nt][3] + bb.y);
        }
    }
    __syncthreads();
}

// ---------------------------------------------------------------------------
// Edge kernel: 128 edges/block
// ---------------------------------------------------------------------------
#define EAS 200

__global__ void __launch_bounds__(256, 1) edge_kernel(
    const float* __restrict__ x, const int* __restrict__ senders,
    const int* __restrict__ receivers, const float* __restrict__ edge_attr,
    const float* __restrict__ b1, const float* __restrict__ b2,
    const float* __restrict__ b3, const float* __restrict__ gam,
    const float* __restrict__ bet, float* __restrict__ out2, int E)
{
    extern __shared__ char smem[];
    __nv_bfloat16* s_ah = reinterpret_cast<__nv_bfloat16*>(smem);
    __nv_bfloat16* s_al = s_ah + 128 * EAS;
    __nv_bfloat16* s_wh = s_al + 128 * EAS;
    __nv_bfloat16* s_wl = s_wh + 9216;
    float* s_out = reinterpret_cast<float*>(s_wh);

    const int tid = threadIdx.x;
    const int e0 = blockIdx.x << 7;

    #pragma unroll
    for (int it = 0; it < 24; it++) {
        int idx = tid + (it << 8);
        int row = idx / 48;
        int k4 = idx - row * 48;
        int e = min(e0 + row, E - 1);
        const float* src;
        if (k4 < 16)      src = edge_attr + (size_t)e * 64 + (k4 << 2);
        else if (k4 < 32) src = x + (size_t)__ldg(receivers + e) * 64 + ((k4 - 16) << 2);
        else              src = x + (size_t)__ldg(senders + e) * 64 + ((k4 - 32) << 2);
        float4 v = *reinterpret_cast<const float4*>(src);
        uint32_t h0, l0, h1, l1;
        split2(v.x, v.y, h0, l0);
        split2(v.z, v.w, h1, l1);
        int base = row * EAS + (k4 << 2);
        *reinterpret_cast<uint2*>(&s_ah[base]) = make_uint2(h0, h1);
        *reinterpret_cast<uint2*>(&s_al[base]) = make_uint2(l0, l1);
    }

    layer_c128<192>(&g_wh[OFF_EW1], &g_wl[OFF_EW1], s_ah, s_al, EAS, s_wh, s_wl, b1, tid);
    layer_c128<128>(&g_wh[OFF_EW2], &g_wl[OFF_EW2], s_ah, s_al, EAS, s_wh, s_wl, b2, tid);
    layer_c64(&g_wh[OFF_EW3], &g_wl[OFF_EW3], s_ah, s_al, EAS, s_wh, s_wl, b3, s_out, tid);

    // LayerNorm + residual + antisymmetric scatter
    const int lane = tid & 31, w = tid >> 5;
    const int cc = lane << 1;
    const float g0 = __ldg(&gam[cc]), g1 = __ldg(&gam[cc + 1]);
    const float be0 = __ldg(&bet[cc]), be1 = __ldg(&bet[cc + 1]);
    #pragma unroll 4
    for (int i = 0; i < 16; i++) {
        int r = (w << 4) + i;
        int e = e0 + r;
        float2 v = *reinterpret_cast<const float2*>(&s_out[r * 68 + cc]);
        float s = v.x + v.y;
        float q = v.x * v.x + v.y * v.y;
        #pragma unroll
        for (int o = 16; o; o >>= 1) {
            s += __shfl_xor_sync(0xffffffffu, s, o);
            q += __shfl_xor_sync(0xffffffffu, q, o);
        }
        float mean = s * 0.015625f;
        float var = q * 0.015625f - mean * mean;
        float rstd = rsqrtf(var + 1e-5f);
        float m0 = (v.x - mean) * rstd * g0 + be0;
        float m1 = (v.y - mean) * rstd * g1 + be1;
        if (e < E) {
            float2 ea = *reinterpret_cast<const float2*>(&edge_attr[(size_t)e * 64 + cc]);
            *reinterpret_cast<float2*>(&out2[(size_t)e * 64 + cc]) =
                make_float2(ea.x + m0, ea.y + m1);
            int rr = __ldg(receivers + e);
            int sn = __ldg(senders + e);
            float* pr = &g_agg[rr * 64 + cc];
            float* ps = &g_agg[sn * 64 + cc];
            asm volatile("red.global.add.v2.f32 [%0], {%1, %2};"
                         :: "l"(pr), "f"(m0), "f"(m1) : "memory");
            asm volatile("red.global.add.v2.f32 [%0], {%1, %2};"
                         :: "l"(ps), "f"(-m0), "f"(-m1) : "memory");
        }
    }
}

// ---------------------------------------------------------------------------
// Node kernel: 128 nodes/block
// ---------------------------------------------------------------------------
#define NAS 136

__global__ void __launch_bounds__(256, 1) node_kernel(
    const float* __restrict__ x,
    const float* __restrict__ b1, const float* __restrict__ b2,
    const float* __restrict__ b3, const float* __restrict__ gam,
    const float* __restrict__ bet, float* __restrict__ out1, int N)
{
    extern __shared__ char smem[];
    __nv_bfloat16* s_ah = reinterpret_cast<__nv_bfloat16*>(smem);
    __nv_bfloat16* s_al = s_ah + 128 * NAS;
    __nv_bfloat16* s_wh = s_al + 128 * NAS;
    __nv_bfloat16* s_wl = s_wh + 9216;
    float* s_out = reinterpret_cast<float*>(s_wh);

    const int tid = threadIdx.x;
    const int n0 = blockIdx.x << 7;

    #pragma unroll
    for (int it = 0; it < 16; it++) {
        int idx = tid + (it << 8);
        int row = idx >> 5;
        int k4 = idx & 31;
        int n = n0 + row;
        float4 v = make_float4(0.f, 0.f, 0.f, 0.f);
        if (n < N) {
            const float* src = (k4 < 16)
                ? x + (size_t)n * 64 + (k4 << 2)
                : g_agg + (size_t)n * 64 + ((k4 - 16) << 2);
            v = *reinterpret_cast<const float4*>(src);
        }
        uint32_t h0, l0, h1, l1;
        split2(v.x, v.y, h0, l0);
        split2(v.z, v.w, h1, l1);
        int base = row * NAS + (k4 << 2);
        *reinterpret_cast<uint2*>(&s_ah[base]) = make_uint2(h0, h1);
        *reinterpret_cast<uint2*>(&s_al[base]) = make_uint2(l0, l1);
    }

    layer_c128<128>(&g_wh[OFF_NW1], &g_wl[OFF_NW1], s_ah, s_al, NAS, s_wh, s_wl, b1, tid);
    layer_c128<128>(&g_wh[OFF_NW2], &g_wl[OFF_NW2], s_ah, s_al, NAS, s_wh, s_wl, b2, tid);
    layer_c64(&g_wh[OFF_NW3], &g_wl[OFF_NW3], s_ah, s_al, NAS, s_wh, s_wl, b3, s_out, tid);

    const int lane = tid & 31, w = tid >> 5;
    const int cc = lane << 1;
    const float g0 = __ldg(&gam[cc]), g1 = __ldg(&gam[cc + 1]);
    const float be0 = __ldg(&bet[cc]), be1 = __ldg(&bet[cc + 1]);
    #pragma unroll 4
    for (int i = 0; i < 16; i++) {
        int r = (w << 4) + i;
        int n = n0 + r;
        float2 v = *reinterpret_cast<const float2*>(&s_out[r * 68 + cc]);
        float s = v.x + v.y;
        float q = v.x * v.x + v.y * v.y;
        #pragma unroll
        for (int o = 16; o; o >>= 1) {
            s += __shfl_xor_sync(0xffffffffu, s, o);
            q += __shfl_xor_sync(0xffffffffu, q, o);
        }
        float mean = s * 0.015625f;
        float var = q * 0.015625f - mean * mean;
        float rstd = rsqrtf(var + 1e-5f);
        if (n < N) {
            float2 xv = *reinterpret_cast<const float2*>(&x[(size_t)n * 64 + cc]);
            float2 o1;
            o1.x = (v.x - mean) * rstd * g0 + be0 + xv.x;
            o1.y = (v.y - mean) * rstd * g1 + be1 + xv.y;
            *reinterpret_cast<float2*>(&out1[(size_t)n * 64 + cc]) = o1;
        }
    }
}

// ---------------------------------------------------------------------------
extern "C" void kernel_launch(void* const* d_in, const int* in_sizes, int n_in,
                              void* d_out, int out_size)
{
    const float* x         = (const float*)d_in[0];
    const int*   senders   = (const int*)  d_in[1];
    const int*   receivers = (const int*)  d_in[2];
    const float* edge_attr = (const float*)d_in[3];
    const float* ew1 = (const float*)d_in[4],  *eb1 = (const float*)d_in[5];
    const float* ew2 = (const float*)d_in[6],  *eb2 = (const float*)d_in[7];
    const float* ew3 = (const float*)d_in[8],  *eb3 = (const float*)d_in[9];
    const float* eg  = (const float*)d_in[10], *ebt = (const float*)d_in[11];
    const float* nw1 = (const float*)d_in[12], *nb1 = (const float*)d_in[13];
    const float* nw2 = (const float*)d_in[14], *nb2 = (const float*)d_in[15];
    const float* nw3 = (const float*)d_in[16], *nb3 = (const float*)d_in[17];
    const float* ng  = (const float*)d_in[18], *nbt = (const float*)d_in[19];

    const int N = in_sizes[0] / 64;
    const int E = in_sizes[1];

    float* out1 = (float*)d_out;
    float* out2 = out1 + (size_t)N * 64;

    const size_t smem_e = (size_t)(128 * EAS * 2 + 18432) * sizeof(__nv_bfloat16);
    const size_t smem_n = (size_t)(128 * NAS * 2 + 18432) * sizeof(__nv_bfloat16);
    cudaFuncSetAttribute(edge_kernel, cudaFuncAttributeMaxDynamicSharedMemorySize, (int)smem_e);
    cudaFuncSetAttribute(node_kernel, cudaFuncAttributeMaxDynamicSharedMemorySize, (int)smem_n);

    // exactly 3 launches before edge_kernel: ncu profiles launch #4 = edge_kernel
    prep_kernel<<<(90112 + 255) / 256, 256>>>(ew1, ew2, ew3, nw1, nw2, nw3);
    zero_agg_kernel<<<(N * 16 + 255) / 256, 256>>>(N * 16);
    pad_kernel<<<1, 32>>>();

    edge_kernel<<<(E + 127) / 128, 256, smem_e>>>(
        x, senders, receivers, edge_attr, eb1, eb2, eb3, eg, ebt, out2, E);

    node_kernel<<<(N + 127) / 128, 256, smem_n>>>(
        x, nb1, nb2, nb3, ng, nbt, out1, N);
}

// round 6
// speedup vs baseline: 1.4445x; 1.4445x over previous
#include <cuda_runtime.h>
#include <cuda_bf16.h>
#include <cstdint>

#define MAX_NODES 100000

__device__ float g_agg[MAX_NODES * 64];
__device__ __nv_bfloat16 g_wh[90112];
__device__ __nv_bfloat16 g_wl[90112];

#define OFF_EW1 0
#define OFF_EW2 24576
#define OFF_EW3 40960
#define OFF_NW1 49152
#define OFF_NW2 65536
#define OFF_NW3 81920

// ---------------------------------------------------------------------------
__global__ void __launch_bounds__(256) zero_agg_kernel(int n4) {
    int i = blockIdx.x * 256 + threadIdx.x;
    if (i < n4) reinterpret_cast<float4*>(g_agg)[i] = make_float4(0.f, 0.f, 0.f, 0.f);
}
__global__ void pad_kernel() {}

// fused: transpose W[k][n] -> Wt[n][k], split fp32 = bf16_hi + bf16_lo
__global__ void __launch_bounds__(256) prep_kernel(
    const float* __restrict__ ew1, const float* __restrict__ ew2,
    const float* __restrict__ ew3, const float* __restrict__ nw1,
    const float* __restrict__ nw2, const float* __restrict__ nw3)
{
    int i = blockIdx.x * 256 + threadIdx.x;
    if (i >= 90112) return;
    const float* W; int K, N, li;
    if      (i < 24576) { W = ew1; K = 192; N = 128; li = i; }
    else if (i < 40960) { W = ew2; K = 128; N = 128; li = i - 24576; }
    else if (i < 49152) { W = ew3; K = 128; N = 64;  li = i - 40960; }
    else if (i < 65536) { W = nw1; K = 128; N = 128; li = i - 49152; }
    else if (i < 81920) { W = nw2; K = 128; N = 128; li = i - 65536; }
    else                { W = nw3; K = 128; N = 64;  li = i - 81920; }
    int n = li / K, k = li - n * K;
    float v = W[(size_t)k * N + n];
    __nv_bfloat16 h = __float2bfloat16_rn(v);
    g_wh[i] = h;
    g_wl[i] = __float2bfloat16_rn(v - __bfloat162float(h));
}

// ---------------------------------------------------------------------------
__device__ __forceinline__ uint32_t smem_u32(const void* p) {
    uint32_t a;
    asm("{ .reg .u64 t; cvta.to.shared.u64 t, %1; cvt.u32.u64 %0, t; }"
        : "=r"(a) : "l"(p));
    return a;
}

__device__ __forceinline__ void split2(float x, float y, uint32_t& h, uint32_t& l) {
    __nv_bfloat162 hh = __floats2bfloat162_rn(x, y);
    float rx = x - __bfloat162float(hh.x);
    float ry = y - __bfloat162float(hh.y);
    __nv_bfloat162 ll = __floats2bfloat162_rn(rx, ry);
    h = reinterpret_cast<uint32_t&>(hh);
    l = reinterpret_cast<uint32_t&>(ll);
}

__device__ __forceinline__ float tanhf_fast(float x) {
    float e;
    asm("ex2.approx.f32 %0, %1;" : "=f"(e) : "f"(x * 2.885390082f)); // exp(2x)
    return 1.0f - __fdividef(2.0f, e + 1.0f);
}

__device__ __forceinline__ void mma16816(float* d, const uint32_t* a,
                                         uint32_t b0, uint32_t b1) {
    asm volatile(
        "mma.sync.aligned.m16n8k16.row.col.f32.bf16.bf16.f32 "
        "{%0,%1,%2,%3}, {%4,%5,%6,%7}, {%8,%9}, {%0,%1,%2,%3};\n"
        : "+f"(d[0]), "+f"(d[1]), "+f"(d[2]), "+f"(d[3])
        : "r"(a[0]), "r"(a[1]), "r"(a[2]), "r"(a[3]), "r"(b0), "r"(b1));
}

__device__ __forceinline__ void ldm4(uint32_t* r, uint32_t addr) {
    asm volatile("ldmatrix.sync.aligned.m8n8.x4.shared.b16 {%0,%1,%2,%3}, [%4];"
                 : "=r"(r[0]), "=r"(r[1]), "=r"(r[2]), "=r"(r[3]) : "r"(addr));
}

#define CP16(dst, src) \
    asm volatile("cp.async.cg.shared.global [%0], [%1], 16;" \
                 :: "r"(dst), "l"(src) : "memory")
#define CP_WAIT() \
    asm volatile("cp.async.commit_group;\n cp.async.wait_group 0;" ::: "memory")

// ---------------------------------------------------------------------------
// C=128 layer. 256 thr = 8 warps, M tile = 64 rows.
// warp w: nhalf = w&1 (64 n-cols), m-strip mb0 = (w>>1)*16.
// Weights staged [128n][72k-stride]; fragments via ldmatrix.x4.
// MMAs grouped by split term (8 independent per group).
// ---------------------------------------------------------------------------
template <int K>
__device__ __forceinline__ void layer_c128(
    const __nv_bfloat16* __restrict__ Wh, const __nv_bfloat16* __restrict__ Wl,
    __nv_bfloat16* s_ah, __nv_bfloat16* s_al, int AS,
    __nv_bfloat16* s_wh, __nv_bfloat16* s_wl,
    const float* __restrict__ bias, int tid)
{
    const int lane = tid & 31, w = tid >> 5;
    const int g = lane >> 2, t = lane & 3;
    const int nhalf = w & 1, mb0 = (w >> 1) << 4;
    const int aro = (lane & 7) + (((lane >> 3) & 1) << 3);
    const int ako = (lane >> 4) << 3;
    const int bro = (lane & 7) + ((lane >> 4) << 3);
    const int bko = ((lane >> 3) & 1) << 3;
    const uint32_t u_ah = smem_u32(s_ah), u_al = smem_u32(s_al);
    const uint32_t u_wh = smem_u32(s_wh), u_wl = smem_u32(s_wl);

    float acc[8][4] = {};

    #pragma unroll
    for (int kc = 0; kc < (K >> 6); kc++) {
        __syncthreads();
        {
            const __nv_bfloat16* sh = Wh + (kc << 6);
            const __nv_bfloat16* sl = Wl + (kc << 6);
            #pragma unroll
            for (int i = 0; i < 4; i++) {
                int idx = tid + (i << 8);
                int n = idx >> 3, k8 = (idx & 7) << 3;
                CP16(u_wh + (uint32_t)(n * 72 + k8) * 2, sh + (size_t)n * K + k8);
                CP16(u_wl + (uint32_t)(n * 72 + k8) * 2, sl + (size_t)n * K + k8);
            }
            CP_WAIT();
        }
        __syncthreads();
        #pragma unroll
        for (int ks = 0; ks < 4; ks++) {
            const int ka = (kc << 6) + (ks << 4);
            const int kw = ks << 4;
            uint32_t ah[4], al[4];
            {
                uint32_t aoff = (uint32_t)((mb0 + aro) * AS + ka + ako) * 2;
                ldm4(ah, u_ah + aoff);
                ldm4(al, u_al + aoff);
            }
            uint32_t bh[4][4], bl[4][4];
            #pragma unroll
            for (int np = 0; np < 4; np++) {
                uint32_t boff = (uint32_t)((((nhalf << 6) + (np << 4)) + bro) * 72 + kw + bko) * 2;
                ldm4(bh[np], u_wh + boff);
                ldm4(bl[np], u_wl + boff);
            }
            #pragma unroll
            for (int np = 0; np < 4; np++) {
                mma16816(acc[2 * np],     ah, bh[np][0], bh[np][1]);
                mma16816(acc[2 * np + 1], ah, bh[np][2], bh[np][3]);
            }
            #pragma unroll
            for (int np = 0; np < 4; np++) {
                mma16816(acc[2 * np],     ah, bl[np][0], bl[np][1]);
                mma16816(acc[2 * np + 1], ah, bl[np][2], bl[np][3]);
            }
            #pragma unroll
            for (int np = 0; np < 4; np++) {
                mma16816(acc[2 * np],     al, bh[np][0], bh[np][1]);
                mma16816(acc[2 * np + 1], al, bh[np][2], bh[np][3]);
            }
        }
    }
    // epilogue: bias + tanh, split-store back into s_ah/s_al
    __syncthreads();
    #pragma unroll
    for (int nt = 0; nt < 8; nt++) {
        int col = (nhalf << 6) + (nt << 3) + (t << 1);
        float2 bb = *reinterpret_cast<const float2*>(&bias[col]);
        int r = mb0 + g;
        uint32_t h, l;
        split2(tanhf_fast(acc[nt][0] + bb.x), tanhf_fast(acc[nt][1] + bb.y), h, l);
        *reinterpret_cast<uint32_t*>(&s_ah[r * AS + col]) = h;
        *reinterpret_cast<uint32_t*>(&s_al[r * AS + col]) = l;
        split2(tanhf_fast(acc[nt][2] + bb.x), tanhf_fast(acc[nt][3] + bb.y), h, l);
        *reinterpret_cast<uint32_t*>(&s_ah[(r + 8) * AS + col]) = h;
        *reinterpret_cast<uint32_t*>(&s_al[(r + 8) * AS + col]) = l;
    }
    __syncthreads();
}

// ---------------------------------------------------------------------------
// C=64 final layer, K=128. Weights [64n][136k-stride] fully staged.
// ---------------------------------------------------------------------------
__device__ __forceinline__ void layer_c64(
    const __nv_bfloat16* __restrict__ Wh, const __nv_bfloat16* __restrict__ Wl,
    const __nv_bfloat16* s_ah, const __nv_bfloat16* s_al, int AS,
    __nv_bfloat16* s_wh, __nv_bfloat16* s_wl,
    const float* __restrict__ bias, float* s_out, int tid)
{
    const int lane = tid & 31, w = tid >> 5;
    const int g = lane >> 2, t = lane & 3;
    const int nhalf = w & 1, mb0 = (w >> 1) << 4;
    const int aro = (lane & 7) + (((lane >> 3) & 1) << 3);
    const int ako = (lane >> 4) << 3;
    const int bro = (lane & 7) + ((lane >> 4) << 3);
    const int bko = ((lane >> 3) & 1) << 3;
    const uint32_t u_ah = smem_u32(s_ah), u_al = smem_u32(s_al);
    const uint32_t u_wh = smem_u32(s_wh), u_wl = smem_u32(s_wl);

    float acc[4][4] = {};

    __syncthreads();
    #pragma unroll
    for (int i = 0; i < 4; i++) {
        int idx = tid + (i << 8);
        int n = idx >> 4, k8 = (idx & 15) << 3;
        CP16(u_wh + (uint32_t)(n * 136 + k8) * 2, Wh + (size_t)n * 128 + k8);
        CP16(u_wl + (uint32_t)(n * 136 + k8) * 2, Wl + (size_t)n * 128 + k8);
    }
    CP_WAIT();
    __syncthreads();

    #pragma unroll
    for (int ks = 0; ks < 8; ks++) {
        const int ka = ks << 4;
        uint32_t ah[4], al[4];
        {
            uint32_t aoff = (uint32_t)((mb0 + aro) * AS + ka + ako) * 2;
            ldm4(ah, u_ah + aoff);
            ldm4(al, u_al + aoff);
        }
        uint32_t bh[2][4], bl[2][4];
        #pragma unroll
        for (int np = 0; np < 2; np++) {
            uint32_t boff = (uint32_t)((((nhalf << 5) + (np << 4)) + bro) * 136 + ka + bko) * 2;
            ldm4(bh[np], u_wh + boff);
            ldm4(bl[np], u_wl + boff);
        }
        #pragma unroll
        for (int np = 0; np < 2; np++) {
            mma16816(acc[2 * np],     ah, bh[np][0], bh[np][1]);
            mma16816(acc[2 * np + 1], ah, bh[np][2], bh[np][3]);
        }
        #pragma unroll
        for (int np = 0; np < 2; np++) {
            mma16816(acc[2 * np],     ah, bl[np][0], bl[np][1]);
            mma16816(acc[2 * np + 1], ah, bl[np][2], bl[np][3]);
        }
        #pragma unroll
        for (int np = 0; np < 2; np++) {
            mma16816(acc[2 * np],     al, bh[np][0], bh[np][1]);
            mma16816(acc[2 * np + 1], al, bh[np][2], bh[np][3]);
        }
    }
    __syncthreads();  // done reading weights; s_out aliases the weight region
    #pragma unroll
    for (int nt = 0; nt < 4; nt++) {
        int col = (nhalf << 5) + (nt << 3) + (t << 1);
        float2 bb = *reinterpret_cast<const float2*>(&bias[col]);
        int r = mb0 + g;
        *reinterpret_cast<float2*>(&s_out[r * 68 + col]) =
            make_float2(acc[nt][0] + bb.x, acc[nt][1] + bb.y);
        *reinterpret_cast<float2*>(&s_out[(r + 8) * 68 + col]) =
            make_float2(acc[nt][2] + bb.x, acc[nt][3] + bb.y);
    }
    __syncthreads();
}

// ---------------------------------------------------------------------------
// Edge kernel: 64 edges/block, 2 CTAs/SM
// ---------------------------------------------------------------------------
#define EAS 200

__global__ void __launch_bounds__(256, 2) edge_kernel(
    const float* __restrict__ x, const int* __restrict__ senders,
    const int* __restrict__ receivers, const float* __restrict__ edge_attr,
    const float* __restrict__ b1, const float* __restrict__ b2,
    const float* __restrict__ b3, const float* __restrict__ gam,
    const float* __restrict__ bet, float* __restrict__ out2, int E)
{
    extern __shared__ char smem[];
    __nv_bfloat16* s_ah = reinterpret_cast<__nv_bfloat16*>(smem);
    __nv_bfloat16* s_al = s_ah + 64 * EAS;
    __nv_bfloat16* s_wh = s_al + 64 * EAS;
    __nv_bfloat16* s_wl = s_wh + 9216;
    float* s_out = reinterpret_cast<float*>(s_wh);

    const int tid = threadIdx.x;
    const int e0 = blockIdx.x << 6;

    #pragma unroll
    for (int it = 0; it < 12; it++) {
        int idx = tid + (it << 8);
        int row = idx / 48;
        int k4 = idx - row * 48;
        int e = min(e0 + row, E - 1);
        const float* src;
        if (k4 < 16)      src = edge_attr + (size_t)e * 64 + (k4 << 2);
        else if (k4 < 32) src = x + (size_t)__ldg(receivers + e) * 64 + ((k4 - 16) << 2);
        else              src = x + (size_t)__ldg(senders + e) * 64 + ((k4 - 32) << 2);
        float4 v = *reinterpret_cast<const float4*>(src);
        uint32_t h0, l0, h1, l1;
        split2(v.x, v.y, h0, l0);
        split2(v.z, v.w, h1, l1);
        int base = row * EAS + (k4 << 2);
        *reinterpret_cast<uint2*>(&s_ah[base]) = make_uint2(h0, h1);
        *reinterpret_cast<uint2*>(&s_al[base]) = make_uint2(l0, l1);
    }

    layer_c128<192>(&g_wh[OFF_EW1], &g_wl[OFF_EW1], s_ah, s_al, EAS, s_wh, s_wl, b1, tid);
    layer_c128<128>(&g_wh[OFF_EW2], &g_wl[OFF_EW2], s_ah, s_al, EAS, s_wh, s_wl, b2, tid);
    layer_c64(&g_wh[OFF_EW3], &g_wl[OFF_EW3], s_ah, s_al, EAS, s_wh, s_wl, b3, s_out, tid);

    // LayerNorm + residual + antisymmetric scatter (8 rows per warp)
    const int lane = tid & 31, w = tid >> 5;
    const int cc = lane << 1;
    const float g0 = __ldg(&gam[cc]), g1 = __ldg(&gam[cc + 1]);
    const float be0 = __ldg(&bet[cc]), be1 = __ldg(&bet[cc + 1]);
    #pragma unroll 4
    for (int i = 0; i < 8; i++) {
        int r = (w << 3) + i;
        int e = e0 + r;
        float2 v = *reinterpret_cast<const float2*>(&s_out[r * 68 + cc]);
        float s = v.x + v.y;
        float q = v.x * v.x + v.y * v.y;
        #pragma unroll
        for (int o = 16; o; o >>= 1) {
            s += __shfl_xor_sync(0xffffffffu, s, o);
            q += __shfl_xor_sync(0xffffffffu, q, o);
        }
        float mean = s * 0.015625f;
        float var = q * 0.015625f - mean * mean;
        float rstd = rsqrtf(var + 1e-5f);
        float m0 = (v.x - mean) * rstd * g0 + be0;
        float m1 = (v.y - mean) * rstd * g1 + be1;
        if (e < E) {
            float2 ea = *reinterpret_cast<const float2*>(&edge_attr[(size_t)e * 64 + cc]);
            *reinterpret_cast<float2*>(&out2[(size_t)e * 64 + cc]) =
                make_float2(ea.x + m0, ea.y + m1);
            int rr = __ldg(receivers + e);
            int sn = __ldg(senders + e);
            float* pr = &g_agg[rr * 64 + cc];
            float* ps = &g_agg[sn * 64 + cc];
            asm volatile("red.global.add.v2.f32 [%0], {%1, %2};"
                         :: "l"(pr), "f"(m0), "f"(m1) : "memory");
            asm volatile("red.global.add.v2.f32 [%0], {%1, %2};"
                         :: "l"(ps), "f"(-m0), "f"(-m1) : "memory");
        }
    }
}

// ---------------------------------------------------------------------------
// Node kernel: 64 nodes/block
// ---------------------------------------------------------------------------
#define NAS 136

__global__ void __launch_bounds__(256, 2) node_kernel(
    const float* __restrict__ x,
    const float* __restrict__ b1, const float* __restrict__ b2,
    const float* __restrict__ b3, const float* __restrict__ gam,
    const float* __restrict__ bet, float* __restrict__ out1, int N)
{
    extern __shared__ char smem[];
    __nv_bfloat16* s_ah = reinterpret_cast<__nv_bfloat16*>(smem);
    __nv_bfloat16* s_al = s_ah + 64 * NAS;
    __nv_bfloat16* s_wh = s_al + 64 * NAS;
    __nv_bfloat16* s_wl = s_wh + 9216;
    float* s_out = reinterpret_cast<float*>(s_wh);

    const int tid = threadIdx.x;
    const int n0 = blockIdx.x << 6;

    #pragma unroll
    for (int it = 0; it < 8; it++) {
        int idx = tid + (it << 8);
        int row = idx >> 5;
        int k4 = idx & 31;
        int n = n0 + row;
        float4 v = make_float4(0.f, 0.f, 0.f, 0.f);
        if (n < N) {
            const float* src = (k4 < 16)
                ? x + (size_t)n * 64 + (k4 << 2)
                : g_agg + (size_t)n * 64 + ((k4 - 16) << 2);
            v = *reinterpret_cast<const float4*>(src);
        }
        uint32_t h0, l0, h1, l1;
        split2(v.x, v.y, h0, l0);
        split2(v.z, v.w, h1, l1);
        int base = row * NAS + (k4 << 2);
        *reinterpret_cast<uint2*>(&s_ah[base]) = make_uint2(h0, h1);
        *reinterpret_cast<uint2*>(&s_al[base]) = make_uint2(l0, l1);
    }

    layer_c128<128>(&g_wh[OFF_NW1], &g_wl[OFF_NW1], s_ah, s_al, NAS, s_wh, s_wl, b1, tid);
    layer_c128<128>(&g_wh[OFF_NW2], &g_wl[OFF_NW2], s_ah, s_al, NAS, s_wh, s_wl, b2, tid);
    layer_c64(&g_wh[OFF_NW3], &g_wl[OFF_NW3], s_ah, s_al, NAS, s_wh, s_wl, b3, s_out, tid);

    const int lane = tid & 31, w = tid >> 5;
    const int cc = lane << 1;
    const float g0 = __ldg(&gam[cc]), g1 = __ldg(&gam[cc + 1]);
    const float be0 = __ldg(&bet[cc]), be1 = __ldg(&bet[cc + 1]);
    #pragma unroll 4
    for (int i = 0; i < 8; i++) {
        int r = (w << 3) + i;
        int n = n0 + r;
        float2 v = *reinterpret_cast<const float2*>(&s_out[r * 68 + cc]);
        float s = v.x + v.y;
        float q = v.x * v.x + v.y * v.y;
        #pragma unroll
        for (int o = 16; o; o >>= 1) {
            s += __shfl_xor_sync(0xffffffffu, s, o);
            q += __shfl_xor_sync(0xffffffffu, q, o);
        }
        float mean = s * 0.015625f;
        float var = q * 0.015625f - mean * mean;
        float rstd = rsqrtf(var + 1e-5f);
        if (n < N) {
            float2 xv = *reinterpret_cast<const float2*>(&x[(size_t)n * 64 + cc]);
            float2 o1;
            o1.x = (v.x - mean) * rstd * g0 + be0 + xv.x;
            o1.y = (v.y - mean) * rstd * g1 + be1 + xv.y;
            *reinterpret_cast<float2*>(&out1[(size_t)n * 64 + cc]) = o1;
        }
    }
}

// ---------------------------------------------------------------------------
extern "C" void kernel_launch(void* const* d_in, const int* in_sizes, int n_in,
                              void* d_out, int out_size)
{
    const float* x         = (const float*)d_in[0];
    const int*   senders   = (const int*)  d_in[1];
    const int*   receivers = (const int*)  d_in[2];
    const float* edge_attr = (const float*)d_in[3];
    const float* ew1 = (const float*)d_in[4],  *eb1 = (const float*)d_in[5];
    const float* ew2 = (const float*)d_in[6],  *eb2 = (const float*)d_in[7];
    const float* ew3 = (const float*)d_in[8],  *eb3 = (const float*)d_in[9];
    const float* eg  = (const float*)d_in[10], *ebt = (const float*)d_in[11];
    const float* nw1 = (const float*)d_in[12], *nb1 = (const float*)d_in[13];
    const float* nw2 = (const float*)d_in[14], *nb2 = (const float*)d_in[15];
    const float* nw3 = (const float*)d_in[16], *nb3 = (const float*)d_in[17];
    const float* ng  = (const float*)d_in[18], *nbt = (const float*)d_in[19];

    const int N = in_sizes[0] / 64;
    const int E = in_sizes[1];

    float* out1 = (float*)d_out;
    float* out2 = out1 + (size_t)N * 64;

    const size_t smem_e = (size_t)(64 * EAS * 2 + 18432) * sizeof(__nv_bfloat16); // 88064
    const size_t smem_n = (size_t)(64 * NAS * 2 + 18432) * sizeof(__nv_bfloat16); // 71680
    cudaFuncSetAttribute(edge_kernel, cudaFuncAttributeMaxDynamicSharedMemorySize, (int)smem_e);
    cudaFuncSetAttribute(node_kernel, cudaFuncAttributeMaxDynamicSharedMemorySize, (int)smem_n);

    // exactly 3 launches before edge_kernel: ncu profiles launch #4 = edge_kernel
    prep_kernel<<<(90112 + 255) / 256, 256>>>(ew1, ew2, ew3, nw1, nw2, nw3);
    zero_agg_kernel<<<(N * 16 + 255) / 256, 256>>>(N * 16);
    pad_kernel<<<1, 32>>>();

    edge_kernel<<<(E + 63) / 64, 256, smem_e>>>(
        x, senders, receivers, edge_attr, eb1, eb2, eb3, eg, ebt, out2, E);

    node_kernel<<<(N + 63) / 64, 256, smem_n>>>(
        x, nb1, nb2, nb3, ng, nbt, out1, N);
}

// round 8
// speedup vs baseline: 1.6169x; 1.1193x over previous
#include <cuda_runtime.h>
#include <cuda_bf16.h>
#include <cstdint>

#define MAX_NODES 100000

__device__ float g_agg[MAX_NODES * 64];
__device__ __nv_bfloat16 g_wh[90112];
__device__ __nv_bfloat16 g_wl[90112];

#define OFF_EW1 0
#define OFF_EW2 24576
#define OFF_EW3 40960
#define OFF_NW1 49152
#define OFF_NW2 65536
#define OFF_NW3 81920

// weight-stage smem row stride (elements). 40 elems = 80 B: 16B-aligned rows,
// and 8-row ldmatrix address set {n*80 mod 128} is conflict-free.
#define WS 40

// ---------------------------------------------------------------------------
__global__ void __launch_bounds__(256) zero_agg_kernel(int n4) {
    int i = blockIdx.x * 256 + threadIdx.x;
    if (i < n4) reinterpret_cast<float4*>(g_agg)[i] = make_float4(0.f, 0.f, 0.f, 0.f);
}
__global__ void pad_kernel() {}

// fused: transpose W[k][n] -> Wt[n][k], split fp32 = bf16_hi + bf16_lo
__global__ void __launch_bounds__(256) prep_kernel(
    const float* __restrict__ ew1, const float* __restrict__ ew2,
    const float* __restrict__ ew3, const float* __restrict__ nw1,
    const float* __restrict__ nw2, const float* __restrict__ nw3)
{
    int i = blockIdx.x * 256 + threadIdx.x;
    if (i >= 90112) return;
    const float* W; int K, N, li;
    if      (i < 24576) { W = ew1; K = 192; N = 128; li = i; }
    else if (i < 40960) { W = ew2; K = 128; N = 128; li = i - 24576; }
    else if (i < 49152) { W = ew3; K = 128; N = 64;  li = i - 40960; }
    else if (i < 65536) { W = nw1; K = 128; N = 128; li = i - 49152; }
    else if (i < 81920) { W = nw2; K = 128; N = 128; li = i - 65536; }
    else                { W = nw3; K = 128; N = 64;  li = i - 81920; }
    int n = li / K, k = li - n * K;
    float v = W[(size_t)k * N + n];
    __nv_bfloat16 h = __float2bfloat16_rn(v);
    g_wh[i] = h;
    g_wl[i] = __float2bfloat16_rn(v - __bfloat162float(h));
}

// ---------------------------------------------------------------------------
__device__ __forceinline__ uint32_t smem_u32(const void* p) {
    uint32_t a;
    asm("{ .reg .u64 t; cvta.to.shared.u64 t, %1; cvt.u32.u64 %0, t; }"
        : "=r"(a) : "l"(p));
    return a;
}

__device__ __forceinline__ void split2(float x, float y, uint32_t& h, uint32_t& l) {
    __nv_bfloat162 hh = __floats2bfloat162_rn(x, y);
    float rx = x - __bfloat162float(hh.x);
    float ry = y - __bfloat162float(hh.y);
    __nv_bfloat162 ll = __floats2bfloat162_rn(rx, ry);
    h = reinterpret_cast<uint32_t&>(hh);
    l = reinterpret_cast<uint32_t&>(ll);
}

__device__ __forceinline__ float tanhf_fast(float x) {
    float e;
    asm("ex2.approx.f32 %0, %1;" : "=f"(e) : "f"(x * 2.885390082f)); // exp(2x)
    return 1.0f - __fdividef(2.0f, e + 1.0f);
}

__device__ __forceinline__ void mma16816(float* d, const uint32_t* a,
                                         uint32_t b0, uint32_t b1) {
    asm volatile(
        "mma.sync.aligned.m16n8k16.row.col.f32.bf16.bf16.f32 "
        "{%0,%1,%2,%3}, {%4,%5,%6,%7}, {%8,%9}, {%0,%1,%2,%3};\n"
        : "+f"(d[0]), "+f"(d[1]), "+f"(d[2]), "+f"(d[3])
        : "r"(a[0]), "r"(a[1]), "r"(a[2]), "r"(a[3]), "r"(b0), "r"(b1));
}

__device__ __forceinline__ void ldm4(uint32_t* r, uint32_t addr) {
    asm volatile("ldmatrix.sync.aligned.m8n8.x4.shared.b16 {%0,%1,%2,%3}, [%4];"
                 : "=r"(r[0]), "=r"(r[1]), "=r"(r[2]), "=r"(r[3]) : "r"(addr));
}

#define CP16(dst, src) \
    asm volatile("cp.async.cg.shared.global [%0], [%1], 16;" \
                 :: "r"(dst), "l"(src) : "memory")
#define CP_WAIT() \
    asm volatile("cp.async.commit_group;\n cp.async.wait_group 0;" ::: "memory")

// stage one K=32 chunk: [nrows n][32 k] bf16 hi+lo, smem row stride WS elems
__device__ __forceinline__ void stage32(
    const __nv_bfloat16* __restrict__ Wh_kc, const __nv_bfloat16* __restrict__ Wl_kc,
    int K, int nrows, uint32_t u_wh, uint32_t u_wl, int tid)
{
    int nsegs = nrows << 2;             // 16B segs per half
    for (int i = tid; i < nsegs; i += 256) {
        int n = i >> 2, k8 = (i & 3) << 3;
        uint32_t doff = (uint32_t)(n * WS + k8) * 2;
        CP16(u_wh + doff, Wh_kc + (size_t)n * K + k8);
        CP16(u_wl + doff, Wl_kc + (size_t)n * K + k8);
    }
    CP_WAIT();
}

// ---------------------------------------------------------------------------
// C=128 layer. 256 thr = 8 warps, M tile = 64 rows.
// warp w: nhalf = w&1 (64 n-cols), m-strip mb0 = (w>>1)*16.
// Weights streamed in K=32 chunks [128 n][WS-stride]; fragments via ldmatrix.
// ---------------------------------------------------------------------------
template <int K>
__device__ __forceinline__ void layer_c128(
    const __nv_bfloat16* __restrict__ Wh, const __nv_bfloat16* __restrict__ Wl,
    __nv_bfloat16* s_ah, __nv_bfloat16* s_al, int AS,
    __nv_bfloat16* s_wh, __nv_bfloat16* s_wl,
    const float* __restrict__ bias, int tid)
{
    const int lane = tid & 31, w = tid >> 5;
    const int g = lane >> 2, t = lane & 3;
    const int nhalf = w & 1, mb0 = (w >> 1) << 4;
    const int aro = (lane & 7) + (((lane >> 3) & 1) << 3);
    const int ako = (lane >> 4) << 3;
    const int bro = (lane & 7) + ((lane >> 4) << 3);
    const int bko = ((lane >> 3) & 1) << 3;
    const uint32_t u_ah = smem_u32(s_ah), u_al = smem_u32(s_al);
    const uint32_t u_wh = smem_u32(s_wh), u_wl = smem_u32(s_wl);

    float acc[8][4] = {};

    #pragma unroll
    for (int kc = 0; kc < (K >> 5); kc++) {
        __syncthreads();
        stage32(Wh + (kc << 5), Wl + (kc << 5), K, 128, u_wh, u_wl, tid);
        __syncthreads();
        #pragma unroll
        for (int ks = 0; ks < 2; ks++) {
            const int ka = (kc << 5) + (ks << 4);
            const int kw = ks << 4;
            uint32_t ah[4], al[4];
            {
                uint32_t aoff = (uint32_t)((mb0 + aro) * AS + ka + ako) * 2;
                ldm4(ah, u_ah + aoff);
                ldm4(al, u_al + aoff);
            }
            #pragma unroll
            for (int np = 0; np < 4; np++) {
                uint32_t boff = (uint32_t)((((nhalf << 6) + (np << 4)) + bro) * WS + kw + bko) * 2;
                uint32_t bh[4], bl[4];
                ldm4(bh, u_wh + boff);
                ldm4(bl, u_wl + boff);
                float* a0 = acc[2 * np];
                float* a1 = acc[2 * np + 1];
                mma16816(a0, ah, bh[0], bh[1]);
                mma16816(a1, ah, bh[2], bh[3]);
                mma16816(a0, ah, bl[0], bl[1]);
                mma16816(a1, ah, bl[2], bl[3]);
                mma16816(a0, al, bh[0], bh[1]);
                mma16816(a1, al, bh[2], bh[3]);
            }
        }
    }
    // epilogue: bias + tanh, split-store back into s_ah/s_al
    __syncthreads();
    #pragma unroll
    for (int nt = 0; nt < 8; nt++) {
        int col = (nhalf << 6) + (nt << 3) + (t << 1);
        float2 bb = *reinterpret_cast<const float2*>(&bias[col]);
        int r = mb0 + g;
        uint32_t h, l;
        split2(tanhf_fast(acc[nt][0] + bb.x), tanhf_fast(acc[nt][1] + bb.y), h, l);
        *reinterpret_cast<uint32_t*>(&s_ah[r * AS + col]) = h;
        *reinterpret_cast<uint32_t*>(&s_al[r * AS + col]) = l;
        split2(tanhf_fast(acc[nt][2] + bb.x), tanhf_fast(acc[nt][3] + bb.y), h, l);
        *reinterpret_cast<uint32_t*>(&s_ah[(r + 8) * AS + col]) = h;
        *reinterpret_cast<uint32_t*>(&s_al[(r + 8) * AS + col]) = l;
    }
    __syncthreads();
}

// ---------------------------------------------------------------------------
// C=64 final layer, K=128, streamed in K=32 chunks [64 n][WS-stride].
// ---------------------------------------------------------------------------
__device__ __forceinline__ void layer_c64(
    const __nv_bfloat16* __restrict__ Wh, const __nv_bfloat16* __restrict__ Wl,
    const __nv_bfloat16* s_ah, const __nv_bfloat16* s_al, int AS,
    __nv_bfloat16* s_wh, __nv_bfloat16* s_wl,
    const float* __restrict__ bias, float* s_out, int tid)
{
    const int lane = tid & 31, w = tid >> 5;
    const int g = lane >> 2, t = lane & 3;
    const int nhalf = w & 1, mb0 = (w >> 1) << 4;
    const int aro = (lane & 7) + (((lane >> 3) & 1) << 3);
    const int ako = (lane >> 4) << 3;
    const int bro = (lane & 7) + ((lane >> 4) << 3);
    const int bko = ((lane >> 3) & 1) << 3;
    const uint32_t u_ah = smem_u32(s_ah), u_al = smem_u32(s_al);
    const uint32_t u_wh = smem_u32(s_wh), u_wl = smem_u32(s_wl);

    float acc[4][4] = {};

    #pragma unroll
    for (int kc = 0; kc < 4; kc++) {
        __syncthreads();
        stage32(Wh + (kc << 5), Wl + (kc << 5), 128, 64, u_wh, u_wl, tid);
        __syncthreads();
        #pragma unroll
        for (int ks = 0; ks < 2; ks++) {
            const int ka = (kc << 5) + (ks << 4);
            const int kw = ks << 4;
            uint32_t ah[4], al[4];
            {
                uint32_t aoff = (uint32_t)((mb0 + aro) * AS + ka + ako) * 2;
                ldm4(ah, u_ah + aoff);
                ldm4(al, u_al + aoff);
            }
            #pragma unroll
            for (int np = 0; np < 2; np++) {
                uint32_t boff = (uint32_t)((((nhalf << 5) + (np << 4)) + bro) * WS + kw + bko) * 2;
                uint32_t bh[4], bl[4];
                ldm4(bh, u_wh + boff);
                ldm4(bl, u_wl + boff);
                float* a0 = acc[2 * np];
                float* a1 = acc[2 * np + 1];
                mma16816(a0, ah, bh[0], bh[1]);
                mma16816(a1, ah, bh[2], bh[3]);
                mma16816(a0, ah, bl[0], bl[1]);
                mma16816(a1, ah, bl[2], bl[3]);
                mma16816(a0, al, bh[0], bh[1]);
                mma16816(a1, al, bh[2], bh[3]);
            }
        }
    }
    __syncthreads();  // done reading weights; s_out aliases the weight region
    #pragma unroll
    for (int nt = 0; nt < 4; nt++) {
        int col = (nhalf << 5) + (nt << 3) + (t << 1);
        float2 bb = *reinterpret_cast<const float2*>(&bias[col]);
        int r = mb0 + g;
        *reinterpret_cast<float2*>(&s_out[r * 68 + col]) =
            make_float2(acc[nt][0] + bb.x, acc[nt][1] + bb.y);
        *reinterpret_cast<float2*>(&s_out[(r + 8) * 68 + col]) =
            make_float2(acc[nt][2] + bb.x, acc[nt][3] + bb.y);
    }
    __syncthreads();
}

// ---------------------------------------------------------------------------
// Edge kernel: 64 edges/block, 3 CTAs/SM
// ---------------------------------------------------------------------------
#define EAS 200

__global__ void __launch_bounds__(256, 3) edge_kernel(
    const float* __restrict__ x, const int* __restrict__ senders,
    const int* __restrict__ receivers, const float* __restrict__ edge_attr,
    const float* __restrict__ b1, const float* __restrict__ b2,
    const float* __restrict__ b3, const float* __restrict__ gam,
    const float* __restrict__ bet, float* __restrict__ out2, int E)
{
    extern __shared__ char smem[];
    __nv_bfloat16* s_ah = reinterpret_cast<__nv_bfloat16*>(smem);
    __nv_bfloat16* s_al = s_ah + 64 * EAS;
    __nv_bfloat16* s_wh = s_al + 64 * EAS;
    __nv_bfloat16* s_wl = s_wh + 128 * WS;
    float* s_out = reinterpret_cast<float*>(s_wh);

    const int tid = threadIdx.x;
    const int e0 = blockIdx.x << 6;

    #pragma unroll
    for (int it = 0; it < 12; it++) {
        int idx = tid + (it << 8);
        int row = idx / 48;
        int k4 = idx - row * 48;
        int e = min(e0 + row, E - 1);
        const float* src;
        if (k4 < 16)      src = edge_attr + (size_t)e * 64 + (k4 << 2);
        else if (k4 < 32) src = x + (size_t)__ldg(receivers + e) * 64 + ((k4 - 16) << 2);
        else              src = x + (size_t)__ldg(senders + e) * 64 + ((k4 - 32) << 2);
        float4 v = *reinterpret_cast<const float4*>(src);
        uint32_t h0, l0, h1, l1;
        split2(v.x, v.y, h0, l0);
        split2(v.z, v.w, h1, l1);
        int base = row * EAS + (k4 << 2);
        *reinterpret_cast<uint2*>(&s_ah[base]) = make_uint2(h0, h1);
        *reinterpret_cast<uint2*>(&s_al[base]) = make_uint2(l0, l1);
    }

    layer_c128<192>(&g_wh[OFF_EW1], &g_wl[OFF_EW1], s_ah, s_al, EAS, s_wh, s_wl, b1, tid);
    layer_c128<128>(&g_wh[OFF_EW2], &g_wl[OFF_EW2], s_ah, s_al, EAS, s_wh, s_wl, b2, tid);
    layer_c64(&g_wh[OFF_EW3], &g_wl[OFF_EW3], s_ah, s_al, EAS, s_wh, s_wl, b3, s_out, tid);

    // LayerNorm + residual + antisymmetric scatter (8 rows per warp)
    const int lane = tid & 31, w = tid >> 5;
    const int cc = lane << 1;
    const float g0 = __ldg(&gam[cc]), g1 = __ldg(&gam[cc + 1]);
    const float be0 = __ldg(&bet[cc]), be1 = __ldg(&bet[cc + 1]);
    #pragma unroll 4
    for (int i = 0; i < 8; i++) {
        int r = (w << 3) + i;
        int e = e0 + r;
        float2 v = *reinterpret_cast<const float2*>(&s_out[r * 68 + cc]);
        float s = v.x + v.y;
        float q = v.x * v.x + v.y * v.y;
        #pragma unroll
        for (int o = 16; o; o >>= 1) {
            s += __shfl_xor_sync(0xffffffffu, s, o);
            q += __shfl_xor_sync(0xffffffffu, q, o);
        }
        float mean = s * 0.015625f;
        float var = q * 0.015625f - mean * mean;
        float rstd = rsqrtf(var + 1e-5f);
        float m0 = (v.x - mean) * rstd * g0 + be0;
        float m1 = (v.y - mean) * rstd * g1 + be1;
        if (e < E) {
            float2 ea = *reinterpret_cast<const float2*>(&edge_attr[(size_t)e * 64 + cc]);
            *reinterpret_cast<float2*>(&out2[(size_t)e * 64 + cc]) =
                make_float2(ea.x + m0, ea.y + m1);
            int rr = __ldg(receivers + e);
            int sn = __ldg(senders + e);
            float* pr = &g_agg[rr * 64 + cc];
            float* ps = &g_agg[sn * 64 + cc];
            asm volatile("red.global.add.v2.f32 [%0], {%1, %2};"
                         :: "l"(pr), "f"(m0), "f"(m1) : "memory");
            asm volatile("red.global.add.v2.f32 [%0], {%1, %2};"
                         :: "l"(ps), "f"(-m0), "f"(-m1) : "memory");
        }
    }
}

// ---------------------------------------------------------------------------
// Node kernel: 64 nodes/block
// ---------------------------------------------------------------------------
#define NAS 136

__global__ void __launch_bounds__(256, 3) node_kernel(
    const float* __restrict__ x,
    const float* __restrict__ b1, const float* __restrict__ b2,
    const float* __restrict__ b3, const float* __restrict__ gam,
    const float* __restrict__ bet, float* __restrict__ out1, int N)
{
    extern __shared__ char smem[];
    __nv_bfloat16* s_ah = reinterpret_cast<__nv_bfloat16*>(smem);
    __nv_bfloat16* s_al = s_ah + 64 * NAS;
    __nv_bfloat16* s_wh = s_al + 64 * NAS;
    __nv_bfloat16* s_wl = s_wh + 128 * WS;
    float* s_out = reinterpret_cast<float*>(s_wh);

    const int tid = threadIdx.x;
    const int n0 = blockIdx.x << 6;

    #pragma unroll
    for (int it = 0; it < 8; it++) {
        int idx = tid + (it << 8);
        int row = idx >> 5;
        int k4 = idx & 31;
        int n = n0 + row;
        float4 v = make_float4(0.f, 0.f, 0.f, 0.f);
        if (n < N) {
            const float* src = (k4 < 16)
                ? x + (size_t)n * 64 + (k4 << 2)
                : g_agg + (size_t)n * 64 + ((k4 - 16) << 2);
            v = *reinterpret_cast<const float4*>(src);
        }
        uint32_t h0, l0, h1, l1;
        split2(v.x, v.y, h0, l0);
        split2(v.z, v.w, h1, l1);
        int base = row * NAS + (k4 << 2);
        *reinterpret_cast<uint2*>(&s_ah[base]) = make_uint2(h0, h1);
        *reinterpret_cast<uint2*>(&s_al[base]) = make_uint2(l0, l1);
    }

    layer_c128<128>(&g_wh[OFF_NW1], &g_wl[OFF_NW1], s_ah, s_al, NAS, s_wh, s_wl, b1, tid);
    layer_c128<128>(&g_wh[OFF_NW2], &g_wl[OFF_NW2], s_ah, s_al, NAS, s_wh, s_wl, b2, tid);
    layer_c64(&g_wh[OFF_NW3], &g_wl[OFF_NW3], s_ah, s_al, NAS, s_wh, s_wl, b3, s_out, tid);

    const int lane = tid & 31, w = tid >> 5;
    const int cc = lane << 1;
    const float g0 = __ldg(&gam[cc]), g1 = __ldg(&gam[cc + 1]);
    const float be0 = __ldg(&bet[cc]), be1 = __ldg(&bet[cc + 1]);
    #pragma unroll 4
    for (int i = 0; i < 8; i++) {
        int r = (w << 3) + i;
        int n = n0 + r;
        float2 v = *reinterpret_cast<const float2*>(&s_out[r * 68 + cc]);
        float s = v.x + v.y;
        float q = v.x * v.x + v.y * v.y;
        #pragma unroll
        for (int o = 16; o; o >>= 1) {
            s += __shfl_xor_sync(0xffffffffu, s, o);
            q += __shfl_xor_sync(0xffffffffu, q, o);
        }
        float mean = s * 0.015625f;
        float var = q * 0.015625f - mean * mean;
        float rstd = rsqrtf(var + 1e-5f);
        if (n < N) {
            float2 xv = *reinterpret_cast<const float2*>(&x[(size_t)n * 64 + cc]);
            float2 o1;
            o1.x = (v.x - mean) * rstd * g0 + be0 + xv.x;
            o1.y = (v.y - mean) * rstd * g1 + be1 + xv.y;
            *reinterpret_cast<float2*>(&out1[(size_t)n * 64 + cc]) = o1;
        }
    }
}

// ---------------------------------------------------------------------------
extern "C" void kernel_launch(void* const* d_in, const int* in_sizes, int n_in,
                              void* d_out, int out_size)
{
    const float* x         = (const float*)d_in[0];
    const int*   senders   = (const int*)  d_in[1];
    const int*   receivers = (const int*)  d_in[2];
    const float* edge_attr = (const float*)d_in[3];
    const float* ew1 = (const float*)d_in[4],  *eb1 = (const float*)d_in[5];
    const float* ew2 = (const float*)d_in[6],  *eb2 = (const float*)d_in[7];
    const float* ew3 = (const float*)d_in[8],  *eb3 = (const float*)d_in[9];
    const float* eg  = (const float*)d_in[10], *ebt = (const float*)d_in[11];
    const float* nw1 = (const float*)d_in[12], *nb1 = (const float*)d_in[13];
    const float* nw2 = (const float*)d_in[14], *nb2 = (const float*)d_in[15];
    const float* nw3 = (const float*)d_in[16], *nb3 = (const float*)d_in[17];
    const float* ng  = (const float*)d_in[18], *nbt = (const float*)d_in[19];

    const int N = in_sizes[0] / 64;
    const int E = in_sizes[1];

    float* out1 = (float*)d_out;
    float* out2 = out1 + (size_t)N * 64;

    const size_t smem_e = (size_t)(64 * EAS * 2 + 2 * 128 * WS) * sizeof(__nv_bfloat16); // 71680
    const size_t smem_n = (size_t)(64 * NAS * 2 + 2 * 128 * WS) * sizeof(__nv_bfloat16); // 55296
    cudaFuncSetAttribute(edge_kernel, cudaFuncAttributeMaxDynamicSharedMemorySize, (int)smem_e);
    cudaFuncSetAttribute(node_kernel, cudaFuncAttributeMaxDynamicSharedMemorySize, (int)smem_n);

    // exactly 3 launches before edge_kernel: ncu profiles launch #4 = edge_kernel
    prep_kernel<<<(90112 + 255) / 256, 256>>>(ew1, ew2, ew3, nw1, nw2, nw3);
    zero_agg_kernel<<<(N * 16 + 255) / 256, 256>>>(N * 16);
    pad_kernel<<<1, 32>>>();

    edge_kernel<<<(E + 63) / 64, 256, smem_e>>>(
        x, senders, receivers, edge_attr, eb1, eb2, eb3, eg, ebt, out2, E);

    node_kernel<<<(N + 63) / 64, 256, smem_n>>>(
        x, nb1, nb2, nb3, ng, nbt, out1, N);
}